// round 2
// baseline (speedup 1.0000x reference)
#include <cuda_runtime.h>
#include <math.h>

// Problem constants
#define Bv   2
#define Dv   2
#define Hv   256
#define Wv   256
#define Cv   256
#define NHd  8     // heads
#define HDd  32    // head dim
#define WSz  8
#define Nw   64    // tokens per window
#define NWIN 1024  // windows per batch (32*32)
#define ROWS 131072 // 2048 windows * 64 tokens  == B*H*W tokens
#define HID  1024

// ---------------------------------------------------------------------------
// Single scratch pool, 192M floats = 768 MB, with liveness-based overlays:
//   [0,   32M)  qin            (live: ln1 .. proj)
//   [32M, 64M)  q              (live: qgemm .. attn)
//   [64M, 128M) kv             (live: kvgemm .. attn)
//   [128M,160M) kvin / att / yn (sequential reuse)
//   [160M,192M) x1             (live: proj .. end)
//   hid = [0, 128M)            (live: mlp1 .. mlp2; overlays qin,q,kv - all dead)
// ---------------------------------------------------------------------------
#define POOL_FLOATS ((size_t)192 * 1024 * 1024)
__device__ __align__(16) float g_pool[POOL_FLOATS];

#define OFF_QIN  ((size_t)0)
#define OFF_Q    ((size_t)32 * 1024 * 1024)
#define OFF_KV   ((size_t)64 * 1024 * 1024)
#define OFF_KVIN ((size_t)128 * 1024 * 1024)
#define OFF_X1   ((size_t)160 * 1024 * 1024)
#define OFF_HID  ((size_t)0)

// ---------------------------------------------------------------------------
// Kernel 1: LayerNorm over C=256 + roll(-4,-4) + window partition scatter.
// One block (64 threads) per token (b,d,h,w). Writes q_in (d==0) / kv_in (d==1).
// ---------------------------------------------------------------------------
__global__ __launch_bounds__(64) void ln1_win_kernel(
    const float* __restrict__ x, const float* __restrict__ g,
    const float* __restrict__ bt,
    float* __restrict__ qin, float* __restrict__ kvin)
{
    int t = blockIdx.x;
    int w = t & 255;
    int h = (t >> 8) & 255;
    int d = (t >> 16) & 1;
    int b = t >> 17;

    const float4* row = (const float4*)(x + (size_t)t * 256);
    float4 v = row[threadIdx.x];
    float s  = v.x + v.y + v.z + v.w;
    float ss = v.x*v.x + v.y*v.y + v.z*v.z + v.w*v.w;
    #pragma unroll
    for (int o = 16; o > 0; o >>= 1) {
        s  += __shfl_xor_sync(0xffffffffu, s,  o);
        ss += __shfl_xor_sync(0xffffffffu, ss, o);
    }
    __shared__ float sh[4];
    int lane = threadIdx.x & 31, wrp = threadIdx.x >> 5;
    if (lane == 0) { sh[wrp] = s; sh[2 + wrp] = ss; }
    __syncthreads();
    s  = sh[0] + sh[1];
    ss = sh[2] + sh[3];
    float mean = s * (1.0f / 256.0f);
    float var  = ss * (1.0f / 256.0f) - mean * mean;
    float inv  = rsqrtf(var + 1e-5f);

    float4 gg = ((const float4*)g )[threadIdx.x];
    float4 bb = ((const float4*)bt)[threadIdx.x];
    float4 o;
    o.x = (v.x - mean) * inv * gg.x + bb.x;
    o.y = (v.y - mean) * inv * gg.y + bb.y;
    o.z = (v.z - mean) * inv * gg.z + bb.z;
    o.w = (v.w - mean) * inv * gg.w + bb.w;

    // destination in shifted coords
    int hs = (h - 4) & 255, ws = (w - 4) & 255;
    int wi = ((hs >> 3) << 5) | (ws >> 3);
    int n  = ((hs & 7) << 3) | (ws & 7);
    size_t drow = ((size_t)((b << 10) | wi)) * 64 + n;
    float* dst = (d == 0 ? qin : kvin) + drow * 256;
    ((float4*)dst)[threadIdx.x] = o;
}

// ---------------------------------------------------------------------------
// Plain LayerNorm (identity layout) for LN2
// ---------------------------------------------------------------------------
__global__ __launch_bounds__(64) void ln_kernel(
    const float* __restrict__ in, const float* __restrict__ g,
    const float* __restrict__ bt, float* __restrict__ out)
{
    size_t t = blockIdx.x;
    const float4* row = (const float4*)(in + t * 256);
    float4 v = row[threadIdx.x];
    float s  = v.x + v.y + v.z + v.w;
    float ss = v.x*v.x + v.y*v.y + v.z*v.z + v.w*v.w;
    #pragma unroll
    for (int o = 16; o > 0; o >>= 1) {
        s  += __shfl_xor_sync(0xffffffffu, s,  o);
        ss += __shfl_xor_sync(0xffffffffu, ss, o);
    }
    __shared__ float sh[4];
    int lane = threadIdx.x & 31, wrp = threadIdx.x >> 5;
    if (lane == 0) { sh[wrp] = s; sh[2 + wrp] = ss; }
    __syncthreads();
    s  = sh[0] + sh[1];
    ss = sh[2] + sh[3];
    float mean = s * (1.0f / 256.0f);
    float var  = ss * (1.0f / 256.0f) - mean * mean;
    float inv  = rsqrtf(var + 1e-5f);

    float4 gg = ((const float4*)g )[threadIdx.x];
    float4 bb = ((const float4*)bt)[threadIdx.x];
    float4 o;
    o.x = (v.x - mean) * inv * gg.x + bb.x;
    o.y = (v.y - mean) * inv * gg.y + bb.y;
    o.z = (v.z - mean) * inv * gg.z + bb.z;
    o.w = (v.w - mean) * inv * gg.w + bb.w;
    ((float4*)(out + t * 256))[threadIdx.x] = o;
}

// ---------------------------------------------------------------------------
// Generic tiled SGEMM: C[M,N] = A[M,K] @ W[N,K]^T  (+ epilogue per MODE)
// BM=BN=128, BK=8, 256 threads, 8x8 microtile per thread.
// MODE 0: Q    out = (acc + bias[c]) * (1/sqrt(32))      -> C (ld 256)
// MODE 1: KV   out = acc + bias[c]                        -> C (ld 512)
// MODE 2: PROJ out = acc + bias[c] + aux1[r,c] + shortcut -> scatter to x1
// MODE 3: MLP1 out = gelu(acc + bias[c])                  -> C (ld 1024)
// MODE 4: MLP2 out = acc + bias[c] + aux1[r,c]            -> C (ld 256)
// ---------------------------------------------------------------------------
template<int MODE>
__global__ __launch_bounds__(256) void gemm_kernel(
    const float* __restrict__ A, const float* __restrict__ Wt,
    const float* __restrict__ bias, float* __restrict__ C,
    int K, int N,
    const float* __restrict__ aux1, const float* __restrict__ aux2)
{
    __shared__ float As[8][128];
    __shared__ float Bs[8][128];

    int tid = threadIdx.x;
    int m0 = blockIdx.y * 128;
    int n0 = blockIdx.x * 128;
    int lr = tid >> 1;
    int lc = (tid & 1) * 4;
    const float* Aptr = A  + (size_t)(m0 + lr) * K + lc;
    const float* Bptr = Wt + (size_t)(n0 + lr) * K + lc;

    int ty = tid >> 4, tx = tid & 15;
    float acc[8][8];
    #pragma unroll
    for (int i = 0; i < 8; i++)
        #pragma unroll
        for (int j = 0; j < 8; j++) acc[i][j] = 0.f;

    for (int k0 = 0; k0 < K; k0 += 8) {
        float4 a = *(const float4*)(Aptr + k0);
        float4 b = *(const float4*)(Bptr + k0);
        As[lc+0][lr] = a.x; As[lc+1][lr] = a.y; As[lc+2][lr] = a.z; As[lc+3][lr] = a.w;
        Bs[lc+0][lr] = b.x; Bs[lc+1][lr] = b.y; Bs[lc+2][lr] = b.z; Bs[lc+3][lr] = b.w;
        __syncthreads();
        #pragma unroll
        for (int kk = 0; kk < 8; kk++) {
            float4 a0 = *(const float4*)&As[kk][ty * 8];
            float4 a1 = *(const float4*)&As[kk][ty * 8 + 4];
            float4 b0 = *(const float4*)&Bs[kk][tx * 8];
            float4 b1 = *(const float4*)&Bs[kk][tx * 8 + 4];
            float ar[8] = {a0.x,a0.y,a0.z,a0.w,a1.x,a1.y,a1.z,a1.w};
            float br[8] = {b0.x,b0.y,b0.z,b0.w,b1.x,b1.y,b1.z,b1.w};
            #pragma unroll
            for (int i = 0; i < 8; i++)
                #pragma unroll
                for (int j = 0; j < 8; j++) acc[i][j] += ar[i] * br[j];
        }
        __syncthreads();
    }

    // epilogue
    #pragma unroll
    for (int i = 0; i < 8; i++) {
        int r = m0 + ty * 8 + i;
        size_t drow = 0;
        const float* shortcut = nullptr;
        if (MODE == 2) {
            int wdx = r >> 6, n = r & 63;
            int b = wdx >> 10, wi = wdx & 1023;
            int hh = ((wi >> 5) << 3) + (n >> 3);
            int ww = ((wi & 31) << 3) + (n & 7);
            hh = (hh + 4) & 255; ww = (ww + 4) & 255;
            drow = ((size_t)b * 256 + hh) * 256 + ww;               // x1 row
            shortcut = aux2 + ((((size_t)b * 2) * 256 + hh) * 256 + ww) * 256; // x[b,0,hh,ww,:]
        }
        #pragma unroll
        for (int j = 0; j < 8; j++) {
            int c = n0 + tx * 8 + j;
            float v = acc[i][j] + bias[c];
            if (MODE == 0) {
                v *= 0.17677669529663687f; // 1/sqrt(32)
                C[(size_t)r * 256 + c] = v;
            } else if (MODE == 1) {
                C[(size_t)r * 512 + c] = v;
            } else if (MODE == 2) {
                v += aux1[(size_t)r * 256 + c] + shortcut[c];
                C[drow * 256 + c] = v;
            } else if (MODE == 3) {
                v = 0.5f * v * (1.0f + erff(v * 0.70710678118654752f));
                C[(size_t)r * (size_t)HID + c] = v;
            } else { // MODE 4
                v += aux1[(size_t)r * 256 + c];
                C[(size_t)r * 256 + c] = v;
            }
        }
    }
}

// ---------------------------------------------------------------------------
// Attention: one block (64 threads) per (window, head).
// scores = q@k^T (+rel-pos bias +mask), softmax, @v.
// ---------------------------------------------------------------------------
__global__ __launch_bounds__(64) void attn_kernel(
    const float* __restrict__ q, const float* __restrict__ kv,
    float* __restrict__ att,
    const float* __restrict__ mask, const float* __restrict__ btab)
{
    int w = blockIdx.x, h = blockIdx.y;
    __shared__ float qs[64][33], ks[64][33], vs[64][33];
    int t = threadIdx.x;

    const float* qbase = q  + (size_t)w * 64 * 256 + h * 32;
    const float* kbase = kv + (size_t)w * 64 * 512 + h * 32;
    const float* vbase = kbase + 256;
    #pragma unroll
    for (int i = 0; i < 8; i++) {
        int idx = i * 64 + t;          // 0..511
        int r = idx >> 3, c4 = (idx & 7) << 2;
        float4 a = *(const float4*)(qbase + (size_t)r * 256 + c4);
        qs[r][c4] = a.x; qs[r][c4+1] = a.y; qs[r][c4+2] = a.z; qs[r][c4+3] = a.w;
        float4 b = *(const float4*)(kbase + (size_t)r * 512 + c4);
        ks[r][c4] = b.x; ks[r][c4+1] = b.y; ks[r][c4+2] = b.z; ks[r][c4+3] = b.w;
        float4 c = *(const float4*)(vbase + (size_t)r * 512 + c4);
        vs[r][c4] = c.x; vs[r][c4+1] = c.y; vs[r][c4+2] = c.z; vs[r][c4+3] = c.w;
    }
    __syncthreads();

    int n = t;
    float qr[32];
    #pragma unroll
    for (int d0 = 0; d0 < 32; d0++) qr[d0] = qs[n][d0];

    const float* mrow = mask + (size_t)(w & 1023) * 4096 + n * 64;
    int nh_ = n >> 3, nw_ = n & 7;

    float s[64];
    float mx = -1e30f;
    #pragma unroll
    for (int m = 0; m < 64; m++) {
        float acc = 0.f;
        #pragma unroll
        for (int d0 = 0; d0 < 32; d0++) acc += qr[d0] * ks[m][d0];
        int idx = (nh_ - (m >> 3) + 7) * 15 + (nw_ - (m & 7) + 7);
        acc += btab[idx * 8 + h] + mrow[m];
        s[m] = acc;
        mx = fmaxf(mx, acc);
    }
    float sum = 0.f;
    #pragma unroll
    for (int m = 0; m < 64; m++) { s[m] = expf(s[m] - mx); sum += s[m]; }
    float inv = 1.0f / sum;

    float o[32];
    #pragma unroll
    for (int d0 = 0; d0 < 32; d0++) o[d0] = 0.f;
    #pragma unroll
    for (int m = 0; m < 64; m++) {
        float p = s[m] * inv;
        #pragma unroll
        for (int d0 = 0; d0 < 32; d0++) o[d0] += p * vs[m][d0];
    }
    float* orow = att + ((size_t)w * 64 + n) * 256 + h * 32;
    #pragma unroll
    for (int d0 = 0; d0 < 32; d0 += 4) {
        float4 ov = make_float4(o[d0], o[d0+1], o[d0+2], o[d0+3]);
        *(float4*)(orow + d0) = ov;
    }
}

// ---------------------------------------------------------------------------
extern "C" void kernel_launch(void* const* d_in, const int* in_sizes, int n_in,
                              void* d_out, int out_size)
{
    const float* x          = (const float*)d_in[0];
    const float* mask       = (const float*)d_in[1];
    const float* g1         = (const float*)d_in[2];
    const float* b1         = (const float*)d_in[3];
    const float* qw         = (const float*)d_in[4];
    const float* qb         = (const float*)d_in[5];
    const float* kvw        = (const float*)d_in[6];
    const float* kvb        = (const float*)d_in[7];
    const float* pw         = (const float*)d_in[8];
    const float* pb         = (const float*)d_in[9];
    const float* bias_table = (const float*)d_in[10];
    const float* g2         = (const float*)d_in[11];
    const float* b2         = (const float*)d_in[12];
    const float* w1         = (const float*)d_in[13];
    const float* bi1        = (const float*)d_in[14];
    const float* w2         = (const float*)d_in[15];
    const float* bi2        = (const float*)d_in[16];
    float* out = (float*)d_out;

    float* pool = nullptr;
    cudaGetSymbolAddress((void**)&pool, g_pool);

    float* qin  = pool + OFF_QIN;
    float* q    = pool + OFF_Q;
    float* kv   = pool + OFF_KV;
    float* kvin = pool + OFF_KVIN;   // then att, then yn (sequential reuse)
    float* x1   = pool + OFF_X1;
    float* att  = kvin;
    float* yn   = kvin;
    float* hid  = pool + OFF_HID;    // overlays qin/q/kv (dead by MLP time)

    // 1. LN1 + shift + window partition
    ln1_win_kernel<<<Bv * Dv * Hv * Wv, 64>>>(x, g1, b1, qin, kvin);

    // 2. q = (q_in @ qw^T + qb) * 1/sqrt(32)
    gemm_kernel<0><<<dim3(2, 1024), 256>>>(qin, qw, qb, q, 256, 256, nullptr, nullptr);

    // 3. kv = kv_in @ kvw^T + kvb
    gemm_kernel<1><<<dim3(4, 1024), 256>>>(kvin, kvw, kvb, kv, 256, 512, nullptr, nullptr);

    // 4. attention (att overwrites kvin slot - kvin is dead now)
    attn_kernel<<<dim3(2048, 8), 64>>>(q, kv, att, mask, bias_table);

    // 5. proj + residual(q_in) + shortcut gather + inverse-roll scatter -> x1
    gemm_kernel<2><<<dim3(2, 1024), 256>>>(att, pw, pb, x1, 256, 256, qin, x);

    // 6. LN2 (yn overwrites att slot - att is dead now)
    ln_kernel<<<ROWS, 64>>>(x1, g2, b2, yn);

    // 7. MLP1 + gelu (hid overlays qin/q/kv - all dead now)
    gemm_kernel<3><<<dim3(8, 1024), 256>>>(yn, w1, bi1, hid, 256, 1024, nullptr, nullptr);

    // 8. MLP2 + residual(x1) -> out
    gemm_kernel<4><<<dim3(2, 1024), 256>>>(hid, w2, bi2, out, 1024, 256, x1, nullptr);
}

// round 4
// speedup vs baseline: 3.9092x; 3.9092x over previous
#include <cuda_runtime.h>
#include <cuda_bf16.h>
#include <math.h>
#include <stdint.h>

// ---------------------------------------------------------------------------
// Problem constants
// ---------------------------------------------------------------------------
#define ROWS 131072        // B*H*W tokens (= 2048 windows * 64)
#define HID  1024
#define MB   ((size_t)1024 * 1024)

// ---------------------------------------------------------------------------
// Scratch pool (bytes) with liveness overlays (same as round 2):
//  [0,128M)    qin_f32   (ln1 -> proj)         } overlaid by hid_bf16 [0,256M)
//  [128M,256M) q_f32     (qgemm -> attn)       }   (both dead before MLP1)
//  [256M,512M) kv_f32    (kvgemm -> attn); yn_bf16 at [256M,320M) after attn
//  [512M,576M) qin_bf16  (ln1 -> qgemm)
//  [576M,640M) kvin_bf16 (ln1 -> kvgemm)
//  [640M,704M) att_bf16  (attn -> proj)
//  [704M,832M) x1_f32    (proj -> end)
//  [832M,...)  weights bf16
// ---------------------------------------------------------------------------
#define POOL_BYTES ((size_t)836 * MB)
__device__ __align__(1024) unsigned char g_pool[POOL_BYTES];

#define OFF_QIN_F32  ((size_t)0)
#define OFF_Q_F32    ((size_t)128 * MB)
#define OFF_KV_F32   ((size_t)256 * MB)
#define OFF_QIN_BF   ((size_t)512 * MB)
#define OFF_KVIN_BF  ((size_t)576 * MB)
#define OFF_ATT_BF   ((size_t)640 * MB)
#define OFF_X1_F32   ((size_t)704 * MB)
#define OFF_WQ_BF    ((size_t)832 * MB)
#define OFF_WKV_BF   (OFF_WQ_BF  + 256 * 256 * 2)
#define OFF_W_P_BF   (OFF_WKV_BF + 512 * 256 * 2)
#define OFF_W1_BF    (OFF_W_P_BF + 256 * 256 * 2)
#define OFF_W2_BF    (OFF_W1_BF  + 1024 * 256 * 2)
#define OFF_HID_BF   ((size_t)0)
#define OFF_YN_BF    ((size_t)256 * MB)

// SW128 swizzle (Swizzle<3,4,3>): XOR bits[6:4] with bits[9:7]; 16B units kept.
// For 128B rows: swizzled(row,c) = row*128 + (c ^ ((row&7)<<4))
#define SWZ(o) ((o) ^ (((o) >> 3) & 0x70))

// bf16 operand tile: 128 rows x 64 cols (128 bytes/row), 16KB, swizzled.
// gmem: tile (mtile, ktile) at ((mtile*(K/64)+ktile) * 8192) elements.

// ---------------------------------------------------------------------------
// PTX helpers (baseline sm_100-safe: cp.async, ldmatrix, mma.sync only)
// ---------------------------------------------------------------------------
__device__ __forceinline__ uint32_t smem_u32(const void* p) {
    uint32_t a;
    asm("{ .reg .u64 t; cvta.to.shared.u64 t, %1; cvt.u32.u64 %0, t; }" : "=r"(a) : "l"(p));
    return a;
}
__device__ __forceinline__ void cp16(uint32_t s, const void* g) {
    asm volatile("cp.async.cg.shared.global [%0], [%1], 16;" :: "r"(s), "l"(g) : "memory");
}
__device__ __forceinline__ void cp_commit() { asm volatile("cp.async.commit_group;" ::: "memory"); }
template<int N> __device__ __forceinline__ void cp_wait() {
    asm volatile("cp.async.wait_group %0;" :: "n"(N) : "memory");
}
__device__ __forceinline__ void ldm_x4(uint32_t& r0, uint32_t& r1, uint32_t& r2, uint32_t& r3, uint32_t addr) {
    asm volatile("ldmatrix.sync.aligned.m8n8.x4.shared.b16 {%0,%1,%2,%3}, [%4];"
                 : "=r"(r0), "=r"(r1), "=r"(r2), "=r"(r3) : "r"(addr));
}
__device__ __forceinline__ void mma_bf16(float* c, const uint32_t* a, uint32_t b0, uint32_t b1) {
    asm volatile(
        "mma.sync.aligned.m16n8k16.row.col.f32.bf16.bf16.f32 "
        "{%0,%1,%2,%3}, {%4,%5,%6,%7}, {%8,%9}, {%0,%1,%2,%3};"
        : "+f"(c[0]), "+f"(c[1]), "+f"(c[2]), "+f"(c[3])
        : "r"(a[0]), "r"(a[1]), "r"(a[2]), "r"(a[3]), "r"(b0), "r"(b1));
}

// ---------------------------------------------------------------------------
// Weight conversion: fp32 [N,K] row-major -> bf16 swizzled tiles
// ---------------------------------------------------------------------------
__global__ __launch_bounds__(256) void convw_kernel(
    const float* __restrict__ src, __nv_bfloat16* __restrict__ dst, int K)
{
    int gid = blockIdx.x * 256 + threadIdx.x;   // one per 8 elements
    int kdiv8 = K >> 3;
    int r  = gid / kdiv8;
    int c0 = (gid - r * kdiv8) << 3;
    const float4* s = (const float4*)(src + (size_t)r * K + c0);
    float4 f0 = s[0], f1 = s[1];
    __nv_bfloat162 p0 = __floats2bfloat162_rn(f0.x, f0.y);
    __nv_bfloat162 p1 = __floats2bfloat162_rn(f0.z, f0.w);
    __nv_bfloat162 p2 = __floats2bfloat162_rn(f1.x, f1.y);
    __nv_bfloat162 p3 = __floats2bfloat162_rn(f1.z, f1.w);
    uint4 v;
    v.x = *(uint32_t*)&p0; v.y = *(uint32_t*)&p1; v.z = *(uint32_t*)&p2; v.w = *(uint32_t*)&p3;
    int mt = r >> 7, kt = c0 >> 6, lr = r & 127, lc = c0 & 63;
    size_t tbase = ((size_t)(mt * (K >> 6) + kt)) << 14;   // bytes
    uint32_t off = SWZ((uint32_t)(lr * 128 + lc * 2));
    *(uint4*)((unsigned char*)dst + tbase + off) = v;
}

// ---------------------------------------------------------------------------
// LN1 + roll(-4,-4) + window partition. Writes qin_f32 (d==0) + bf16 tiles.
// ---------------------------------------------------------------------------
__global__ __launch_bounds__(64) void ln1_win_kernel(
    const float* __restrict__ x, const float* __restrict__ g, const float* __restrict__ bt,
    float* __restrict__ qin_f32, __nv_bfloat16* __restrict__ qin_bf,
    __nv_bfloat16* __restrict__ kvin_bf)
{
    int t = blockIdx.x;
    int w = t & 255, h = (t >> 8) & 255, d = (t >> 16) & 1, b = t >> 17;

    float4 v = ((const float4*)(x + (size_t)t * 256))[threadIdx.x];
    float s  = v.x + v.y + v.z + v.w;
    float ss = v.x*v.x + v.y*v.y + v.z*v.z + v.w*v.w;
    #pragma unroll
    for (int o = 16; o > 0; o >>= 1) {
        s  += __shfl_xor_sync(0xffffffffu, s,  o);
        ss += __shfl_xor_sync(0xffffffffu, ss, o);
    }
    __shared__ float sh[4];
    int lane = threadIdx.x & 31, wrp = threadIdx.x >> 5;
    if (lane == 0) { sh[wrp] = s; sh[2 + wrp] = ss; }
    __syncthreads();
    s = sh[0] + sh[1]; ss = sh[2] + sh[3];
    float mean = s * (1.0f / 256.0f);
    float inv  = rsqrtf(ss * (1.0f / 256.0f) - mean * mean + 1e-5f);

    float4 gg = ((const float4*)g )[threadIdx.x];
    float4 bb = ((const float4*)bt)[threadIdx.x];
    float4 o;
    o.x = (v.x - mean) * inv * gg.x + bb.x;
    o.y = (v.y - mean) * inv * gg.y + bb.y;
    o.z = (v.z - mean) * inv * gg.z + bb.z;
    o.w = (v.w - mean) * inv * gg.w + bb.w;

    int hs = (h - 4) & 255, ws = (w - 4) & 255;
    int wi = ((hs >> 3) << 5) | (ws >> 3);
    int n  = ((hs & 7) << 3) | (ws & 7);
    int drow = (((b << 10) | wi) << 6) | n;     // window-order row

    int c0 = threadIdx.x * 4;
    __nv_bfloat162 lo = __floats2bfloat162_rn(o.x, o.y);
    __nv_bfloat162 hi = __floats2bfloat162_rn(o.z, o.w);
    uint2 bfv; bfv.x = *(uint32_t*)&lo; bfv.y = *(uint32_t*)&hi;
    int mt = drow >> 7, kt = c0 >> 6, lr = drow & 127, lc = c0 & 63;
    size_t tbase = ((size_t)(mt * 4 + kt)) << 14;
    uint32_t off = SWZ((uint32_t)(lr * 128 + lc * 2));

    if (d == 0) {
        ((float4*)(qin_f32 + (size_t)drow * 256))[threadIdx.x] = o;
        *(uint2*)((unsigned char*)qin_bf + tbase + off) = bfv;
    } else {
        *(uint2*)((unsigned char*)kvin_bf + tbase + off) = bfv;
    }
}

// ---------------------------------------------------------------------------
// LN2: x1 fp32 (token layout) -> yn bf16 tiles
// ---------------------------------------------------------------------------
__global__ __launch_bounds__(64) void ln2_kernel(
    const float* __restrict__ in, const float* __restrict__ g, const float* __restrict__ bt,
    __nv_bfloat16* __restrict__ out_bf)
{
    int t = blockIdx.x;
    float4 v = ((const float4*)(in + (size_t)t * 256))[threadIdx.x];
    float s  = v.x + v.y + v.z + v.w;
    float ss = v.x*v.x + v.y*v.y + v.z*v.z + v.w*v.w;
    #pragma unroll
    for (int o = 16; o > 0; o >>= 1) {
        s  += __shfl_xor_sync(0xffffffffu, s,  o);
        ss += __shfl_xor_sync(0xffffffffu, ss, o);
    }
    __shared__ float sh[4];
    int lane = threadIdx.x & 31, wrp = threadIdx.x >> 5;
    if (lane == 0) { sh[wrp] = s; sh[2 + wrp] = ss; }
    __syncthreads();
    s = sh[0] + sh[1]; ss = sh[2] + sh[3];
    float mean = s * (1.0f / 256.0f);
    float inv  = rsqrtf(ss * (1.0f / 256.0f) - mean * mean + 1e-5f);

    float4 gg = ((const float4*)g )[threadIdx.x];
    float4 bb = ((const float4*)bt)[threadIdx.x];
    float4 o;
    o.x = (v.x - mean) * inv * gg.x + bb.x;
    o.y = (v.y - mean) * inv * gg.y + bb.y;
    o.z = (v.z - mean) * inv * gg.z + bb.z;
    o.w = (v.w - mean) * inv * gg.w + bb.w;

    int c0 = threadIdx.x * 4;
    __nv_bfloat162 lo = __floats2bfloat162_rn(o.x, o.y);
    __nv_bfloat162 hi = __floats2bfloat162_rn(o.z, o.w);
    uint2 bfv; bfv.x = *(uint32_t*)&lo; bfv.y = *(uint32_t*)&hi;
    int mt = t >> 7, kt = c0 >> 6, lr = t & 127, lc = c0 & 63;
    size_t tbase = ((size_t)(mt * 4 + kt)) << 14;
    uint32_t off = SWZ((uint32_t)(lr * 128 + lc * 2));
    *(uint2*)((unsigned char*)out_bf + tbase + off) = bfv;
}

// ---------------------------------------------------------------------------
// HMMA bf16 GEMM: C[M,N] = A[M,K] @ W[N,K]^T.  CTA tile 128x128, 8 warps (2Mx4N),
// warp tile 64x32, mma.m16n8k16, cp.async double-buffered K-chunks of 64.
// Epilogue per MODE:
//  0: q_f32[r*256+c]   = (acc + bias[c]) / sqrt(32)
//  1: kv_f32[r*512+c]  = acc + bias[c]
//  2: x1[scatter]      = acc + bias[c] + qin_f32[r,c] + x[b,0,hh,ww,c]
//  3: hid_bf[tiles]    = gelu(acc + bias[c])
//  4: out[r*256+c]     = acc + bias[c] + x1[r,c]
// ---------------------------------------------------------------------------
template<int MODE>
__global__ __launch_bounds__(256) void gemm_mma(
    const __nv_bfloat16* __restrict__ A, const __nv_bfloat16* __restrict__ B,
    const float* __restrict__ bias, void* __restrict__ Cout, int K,
    const float* __restrict__ aux1, const float* __restrict__ aux2)
{
    extern __shared__ __align__(1024) unsigned char dsm[];
    uint32_t sbase = smem_u32(dsm);
    uint32_t stA[2] = { sbase,         sbase + 32768 };
    uint32_t stB[2] = { sbase + 16384, sbase + 49152 };

    int tid = threadIdx.x, wid = tid >> 5, lane = tid & 31;
    int KC = K >> 6;
    const unsigned char* Ab = (const unsigned char*)A + (((size_t)blockIdx.y * KC) << 14);
    const unsigned char* Bb = (const unsigned char*)B + (((size_t)blockIdx.x * KC) << 14);

    auto load_chunk = [&](int kc, int s) {
        const unsigned char* ga = Ab + ((size_t)kc << 14);
        const unsigned char* gb = Bb + ((size_t)kc << 14);
        #pragma unroll
        for (int i = 0; i < 4; i++) {
            int o = tid * 16 + i * 4096;
            cp16(stA[s] + o, ga + o);
            cp16(stB[s] + o, gb + o);
        }
        cp_commit();
    };

    // warp/lane geometry
    int wm = wid & 1, wn = wid >> 1;
    int am0 = wm * 64, bn0 = wn * 32;
    int row_off = ((lane >> 3) & 1) * 8 + (lane & 7);  // ldmatrix source row-in-16
    int colbit  = ((lane >> 4) & 1) * 16;              // 16B chunk select
    uint32_t xr = (uint32_t)((lane & 7) << 4);         // swizzle XOR (row&7)<<4
    uint32_t aro[4], bro[2];
    #pragma unroll
    for (int ma = 0; ma < 4; ma++) aro[ma] = (uint32_t)((am0 + ma * 16 + row_off) * 128);
    #pragma unroll
    for (int nb = 0; nb < 2; nb++) bro[nb] = (uint32_t)((bn0 + nb * 16 + row_off) * 128);

    float acc[4][4][4];
    #pragma unroll
    for (int ma = 0; ma < 4; ma++)
        #pragma unroll
        for (int na = 0; na < 4; na++)
            #pragma unroll
            for (int i = 0; i < 4; i++) acc[ma][na][i] = 0.f;

    load_chunk(0, 0);
    for (int kc = 0; kc < KC; kc++) {
        int s = kc & 1;
        if (kc + 1 < KC) { load_chunk(kc + 1, s ^ 1); cp_wait<1>(); }
        else             { cp_wait<0>(); }
        __syncthreads();

        #pragma unroll
        for (int ks = 0; ks < 4; ks++) {
            uint32_t cbyte = (uint32_t)(ks * 32 + colbit) ^ xr;
            uint32_t a[4][4], b[2][4];
            #pragma unroll
            for (int ma = 0; ma < 4; ma++)
                ldm_x4(a[ma][0], a[ma][1], a[ma][2], a[ma][3], stA[s] + aro[ma] + cbyte);
            #pragma unroll
            for (int nb = 0; nb < 2; nb++)
                ldm_x4(b[nb][0], b[nb][1], b[nb][2], b[nb][3], stB[s] + bro[nb] + cbyte);
            #pragma unroll
            for (int ma = 0; ma < 4; ma++)
                #pragma unroll
                for (int na = 0; na < 4; na++)
                    mma_bf16(acc[ma][na], a[ma], b[na >> 1][na & 1], b[na >> 1][2 + (na & 1)]);
        }
        __syncthreads();
    }

    // ---------------- epilogue ----------------
    int lm = lane >> 2, ln = (lane & 3) * 2;
    int m_cta = blockIdx.y * 128;
    int n_cta = blockIdx.x * 128;

    float2 bias2[4];
    #pragma unroll
    for (int na = 0; na < 4; na++)
        bias2[na] = *(const float2*)(bias + n_cta + bn0 + na * 8 + ln);

    #pragma unroll
    for (int ma = 0; ma < 4; ma++) {
        #pragma unroll
        for (int half = 0; half < 2; half++) {
            int r = m_cta + am0 + ma * 16 + lm + half * 8;
            // MODE 2 scatter mapping
            size_t drow = 0; const float* shortcut = nullptr;
            if (MODE == 2) {
                int wdx = r >> 6, n = r & 63;
                int b = wdx >> 10, wi = wdx & 1023;
                int hh = ((wi >> 5) << 3) + (n >> 3);
                int ww = ((wi & 31) << 3) + (n & 7);
                hh = (hh + 4) & 255; ww = (ww + 4) & 255;
                drow = ((size_t)b * 256 + hh) * 256 + ww;
                shortcut = aux2 + ((((size_t)b * 2) * 256 + hh) * 256 + ww) * 256;
            }
            #pragma unroll
            for (int na = 0; na < 4; na++) {
                int c = n_cta + bn0 + na * 8 + ln;
                float v0 = acc[ma][na][half * 2]     + bias2[na].x;
                float v1 = acc[ma][na][half * 2 + 1] + bias2[na].y;
                if (MODE == 0) {
                    v0 *= 0.17677669529663687f; v1 *= 0.17677669529663687f;
                    *(float2*)((float*)Cout + (size_t)r * 256 + c) = make_float2(v0, v1);
                } else if (MODE == 1) {
                    *(float2*)((float*)Cout + (size_t)r * 512 + c) = make_float2(v0, v1);
                } else if (MODE == 2) {
                    float2 av = *(const float2*)(aux1 + (size_t)r * 256 + c);
                    float2 sv = *(const float2*)(shortcut + c);
                    *(float2*)((float*)Cout + drow * 256 + c) =
                        make_float2(v0 + av.x + sv.x, v1 + av.y + sv.y);
                } else if (MODE == 3) {
                    v0 = 0.5f * v0 * (1.0f + erff(v0 * 0.70710678118654752f));
                    v1 = 0.5f * v1 * (1.0f + erff(v1 * 0.70710678118654752f));
                    int mt = r >> 7, lr = r & 127;
                    int kt = c >> 6, lc = c & 63;
                    size_t tbase = ((size_t)(mt * 16 + kt)) << 14;
                    uint32_t off = SWZ((uint32_t)(lr * 128 + lc * 2));
                    __nv_bfloat162 p = __floats2bfloat162_rn(v0, v1);
                    *(uint32_t*)((unsigned char*)Cout + tbase + off) = *(uint32_t*)&p;
                } else { // MODE 4
                    float2 av = *(const float2*)(aux1 + (size_t)r * 256 + c);
                    *(float2*)((float*)Cout + (size_t)r * 256 + c) =
                        make_float2(v0 + av.x, v1 + av.y);
                }
            }
        }
    }
}

// ---------------------------------------------------------------------------
// Attention: one block (64 threads) per (window, head). fp32 in, bf16-tile out.
// ---------------------------------------------------------------------------
__global__ __launch_bounds__(64) void attn_kernel(
    const float* __restrict__ q, const float* __restrict__ kv,
    __nv_bfloat16* __restrict__ att_bf,
    const float* __restrict__ mask, const float* __restrict__ btab)
{
    int w = blockIdx.x, h = blockIdx.y;
    __shared__ float qs[64][33], ks[64][33], vs[64][33];
    int t = threadIdx.x;

    const float* qbase = q  + (size_t)w * 64 * 256 + h * 32;
    const float* kbase = kv + (size_t)w * 64 * 512 + h * 32;
    const float* vbase = kbase + 256;
    #pragma unroll
    for (int i = 0; i < 8; i++) {
        int idx = i * 64 + t;
        int r = idx >> 3, c4 = (idx & 7) << 2;
        float4 a = *(const float4*)(qbase + (size_t)r * 256 + c4);
        qs[r][c4] = a.x; qs[r][c4+1] = a.y; qs[r][c4+2] = a.z; qs[r][c4+3] = a.w;
        float4 b = *(const float4*)(kbase + (size_t)r * 512 + c4);
        ks[r][c4] = b.x; ks[r][c4+1] = b.y; ks[r][c4+2] = b.z; ks[r][c4+3] = b.w;
        float4 c = *(const float4*)(vbase + (size_t)r * 512 + c4);
        vs[r][c4] = c.x; vs[r][c4+1] = c.y; vs[r][c4+2] = c.z; vs[r][c4+3] = c.w;
    }
    __syncthreads();

    int n = t;
    float qr[32];
    #pragma unroll
    for (int d0 = 0; d0 < 32; d0++) qr[d0] = qs[n][d0];

    const float* mrow = mask + (size_t)(w & 1023) * 4096 + n * 64;
    int nh_ = n >> 3, nw_ = n & 7;

    float s[64];
    float mx = -1e30f;
    #pragma unroll
    for (int m = 0; m < 64; m++) {
        float acc = 0.f;
        #pragma unroll
        for (int d0 = 0; d0 < 32; d0++) acc += qr[d0] * ks[m][d0];
        int idx = (nh_ - (m >> 3) + 7) * 15 + (nw_ - (m & 7) + 7);
        acc += btab[idx * 8 + h] + mrow[m];
        s[m] = acc;
        mx = fmaxf(mx, acc);
    }
    float sum = 0.f;
    #pragma unroll
    for (int m = 0; m < 64; m++) { s[m] = expf(s[m] - mx); sum += s[m]; }
    float inv = 1.0f / sum;

    float o[32];
    #pragma unroll
    for (int d0 = 0; d0 < 32; d0++) o[d0] = 0.f;
    #pragma unroll
    for (int m = 0; m < 64; m++) {
        float p = s[m] * inv;
        #pragma unroll
        for (int d0 = 0; d0 < 32; d0++) o[d0] += p * vs[m][d0];
    }

    // store bf16 tiles: row r = w*64+n, cols h*32..h*32+31
    int r = (w << 6) | n;
    int mt = r >> 7, lr = r & 127;
    int kt = h >> 1, lc0 = (h & 1) * 32;
    size_t tbase = ((size_t)(mt * 4 + kt)) << 14;
    #pragma unroll
    for (int d0 = 0; d0 < 32; d0 += 8) {
        uint32_t off = SWZ((uint32_t)(lr * 128 + (lc0 + d0) * 2));
        __nv_bfloat162 p0 = __floats2bfloat162_rn(o[d0],   o[d0+1]);
        __nv_bfloat162 p1 = __floats2bfloat162_rn(o[d0+2], o[d0+3]);
        __nv_bfloat162 p2 = __floats2bfloat162_rn(o[d0+4], o[d0+5]);
        __nv_bfloat162 p3 = __floats2bfloat162_rn(o[d0+6], o[d0+7]);
        uint4 v; v.x = *(uint32_t*)&p0; v.y = *(uint32_t*)&p1;
        v.z = *(uint32_t*)&p2; v.w = *(uint32_t*)&p3;
        *(uint4*)((unsigned char*)att_bf + tbase + off) = v;
    }
}

// ---------------------------------------------------------------------------
extern "C" void kernel_launch(void* const* d_in, const int* in_sizes, int n_in,
                              void* d_out, int out_size)
{
    const float* x          = (const float*)d_in[0];
    const float* mask       = (const float*)d_in[1];
    const float* g1         = (const float*)d_in[2];
    const float* b1         = (const float*)d_in[3];
    const float* qw         = (const float*)d_in[4];
    const float* qb         = (const float*)d_in[5];
    const float* kvw        = (const float*)d_in[6];
    const float* kvb        = (const float*)d_in[7];
    const float* pw         = (const float*)d_in[8];
    const float* pb         = (const float*)d_in[9];
    const float* bias_table = (const float*)d_in[10];
    const float* g2         = (const float*)d_in[11];
    const float* b2         = (const float*)d_in[12];
    const float* w1         = (const float*)d_in[13];
    const float* bi1        = (const float*)d_in[14];
    const float* w2         = (const float*)d_in[15];
    const float* bi2        = (const float*)d_in[16];
    float* out = (float*)d_out;

    unsigned char* pool = nullptr;
    cudaGetSymbolAddress((void**)&pool, g_pool);

    float*          qin_f32 = (float*)(pool + OFF_QIN_F32);
    float*          q_f32   = (float*)(pool + OFF_Q_F32);
    float*          kv_f32  = (float*)(pool + OFF_KV_F32);
    __nv_bfloat16*  qin_bf  = (__nv_bfloat16*)(pool + OFF_QIN_BF);
    __nv_bfloat16*  kvin_bf = (__nv_bfloat16*)(pool + OFF_KVIN_BF);
    __nv_bfloat16*  att_bf  = (__nv_bfloat16*)(pool + OFF_ATT_BF);
    float*          x1      = (float*)(pool + OFF_X1_F32);
    __nv_bfloat16*  wq_bf   = (__nv_bfloat16*)(pool + OFF_WQ_BF);
    __nv_bfloat16*  wkv_bf  = (__nv_bfloat16*)(pool + OFF_WKV_BF);
    __nv_bfloat16*  wp_bf   = (__nv_bfloat16*)(pool + OFF_W_P_BF);
    __nv_bfloat16*  w1_bf   = (__nv_bfloat16*)(pool + OFF_W1_BF);
    __nv_bfloat16*  w2_bf   = (__nv_bfloat16*)(pool + OFF_W2_BF);
    __nv_bfloat16*  hid_bf  = (__nv_bfloat16*)(pool + OFF_HID_BF);
    __nv_bfloat16*  yn_bf   = (__nv_bfloat16*)(pool + OFF_YN_BF);

    const int SMEM = 65536;
    cudaFuncSetAttribute(gemm_mma<0>, cudaFuncAttributeMaxDynamicSharedMemorySize, SMEM);
    cudaFuncSetAttribute(gemm_mma<1>, cudaFuncAttributeMaxDynamicSharedMemorySize, SMEM);
    cudaFuncSetAttribute(gemm_mma<2>, cudaFuncAttributeMaxDynamicSharedMemorySize, SMEM);
    cudaFuncSetAttribute(gemm_mma<3>, cudaFuncAttributeMaxDynamicSharedMemorySize, SMEM);
    cudaFuncSetAttribute(gemm_mma<4>, cudaFuncAttributeMaxDynamicSharedMemorySize, SMEM);

    // weight conversion (fp32 -> bf16 swizzled tiles)
    convw_kernel<<<(256 * 256 / 8) / 256, 256>>>(qw,  wq_bf,  256);
    convw_kernel<<<(512 * 256 / 8) / 256, 256>>>(kvw, wkv_bf, 256);
    convw_kernel<<<(256 * 256 / 8) / 256, 256>>>(pw,  wp_bf,  256);
    convw_kernel<<<(1024 * 256 / 8) / 256, 256>>>(w1, w1_bf,  256);
    convw_kernel<<<(256 * 1024 / 8) / 256, 256>>>(w2, w2_bf, 1024);

    // 1. LN1 + shift + window partition
    ln1_win_kernel<<<2 * 2 * 256 * 256, 64>>>(x, g1, b1, qin_f32, qin_bf, kvin_bf);

    // 2. Q GEMM (fp32 out for attention)
    gemm_mma<0><<<dim3(2, 1024), 256, SMEM>>>(qin_bf, wq_bf, qb, q_f32, 256, nullptr, nullptr);

    // 3. KV GEMM (fp32 out for attention)
    gemm_mma<1><<<dim3(4, 1024), 256, SMEM>>>(kvin_bf, wkv_bf, kvb, kv_f32, 256, nullptr, nullptr);

    // 4. attention -> att bf16 tiles
    attn_kernel<<<dim3(2048, 8), 64>>>(q_f32, kv_f32, att_bf, mask, bias_table);

    // 5. proj + residual(q_in fp32) + shortcut + inverse-roll scatter -> x1 fp32
    gemm_mma<2><<<dim3(2, 1024), 256, SMEM>>>(att_bf, wp_bf, pb, x1, 256, qin_f32, x);

    // 6. LN2 -> yn bf16 tiles (overlays kv_f32, dead)
    ln2_kernel<<<ROWS, 64>>>(x1, g2, b2, yn_bf);

    // 7. MLP1 + gelu -> hid bf16 tiles (overlays qin_f32/q_f32, dead)
    gemm_mma<3><<<dim3(8, 1024), 256, SMEM>>>(yn_bf, w1_bf, bi1, hid_bf, 256, nullptr, nullptr);

    // 8. MLP2 + residual(x1) -> out fp32
    gemm_mma<4><<<dim3(2, 1024), 256, SMEM>>>(hid_bf, w2_bf, bi2, out, 1024, x1, nullptr);
}